// round 6
// baseline (speedup 1.0000x reference)
#include <cuda_runtime.h>
#include <cstdint>

typedef unsigned long long ull;

#define D1 270
#define KK 32
#define CC 60
#define BB 64
#define TT 4096
#define KL (KK*KK)        // 1024

// ---------------- scratch (no allocs allowed) ----------------
__device__ float g_cos[KL * CC];   // [kl][c]
__device__ float g_sin[KL * CC];
__device__ float g_w[D1 * CC];     // [j][c]

// ---------------- f32x2 helpers ----------------
__device__ __forceinline__ ull fma2(ull a, ull b, ull c) {
    ull d;
    asm("fma.rn.f32x2 %0, %1, %2, %3;" : "=l"(d) : "l"(a), "l"(b), "l"(c));
    return d;
}

// ---------------- K0: alignment dummy (keeps ncu -s 5 -c 1 on k_mix) -------
__global__ void k_nop() {}

// ---------------- K1: sin/cos tables ----------------
__global__ void k_tables(const float* __restrict__ loc) {
    int idx = blockIdx.x * blockDim.x + threadIdx.x;
    if (idx >= KL * CC) return;
    int kl = idx / CC;
    int c  = idx - kl * CC;
    int k = kl >> 5, l = kl & 31;
    float t = (float)k * loc[2 * c] + (float)l * loc[2 * c + 1];
    float s, co;
    sincosf(6.283185307179586f * t, &s, &co);
    g_cos[idx] = co;
    g_sin[idx] = s;
}

// ---------------- K2: a[j,c] + softmax over c -> g_w ----------------
// 45 blocks x 6 j each (45*6 = 270): table traffic 45x full-table instead of 270x.
__global__ __launch_bounds__(384) void k_weights(const float* __restrict__ z_re,
                                                 const float* __restrict__ z_im) {
    int tid = threadIdx.x;          // 384 threads
    int c   = tid & 63;
    int row = tid >> 6;             // 0..5
    int j   = blockIdx.x * 6 + row;

    float acc = 0.f;
    if (c < CC) {
        const float* zr = z_re + (size_t)j * KL;
        const float* zi = z_im + (size_t)j * KL;
#pragma unroll 8
        for (int kl = 0; kl < KL; kl++) {
            acc += zr[kl] * g_cos[kl * CC + c] + zi[kl] * g_sin[kl * CC + c];
        }
    }
    __shared__ float aval[6][64];
    __shared__ float red[6][2];
    aval[row][c] = acc;
    __syncthreads();
    if (c == 0) {
        float m = -1e30f;
        for (int i = 0; i < CC; i++) m = fmaxf(m, aval[row][i]);
        float ssum = 0.f;
        for (int i = 0; i < CC; i++) ssum += expf(aval[row][i] - m);
        red[row][0] = m;
        red[row][1] = ssum;
    }
    __syncthreads();
    if (c < CC) {
        g_w[j * CC + c] = expf(aval[row][c] - red[row][0]) / red[row][1];
    }
}

// ---------------- K3: out[b,j,t] = sum_c w[j,c] * X[b,c,t] ----------------
// Grid (16,64). Block 256 = 64 tq (x4 t) x 4 jg (x12 j). 48 j/iter, 6 iters (288 pad).
// Per c per warp: 1 LDS.128 (X) + 6 LDS.128 (w pairs, broadcast) -> 24 FFMA2.
#define JPB 48                      // j per iteration
#define SMEM3 (CC * 256 * 4 + CC * JPB * 8)   // 61440 + 23040 = 84480 B

__global__ __launch_bounds__(256) void k_mix(const float* __restrict__ X,
                                             float* __restrict__ out) {
    extern __shared__ float sm[];
    float* Xs  = sm;                           // [c][256]
    ull*   ws2 = (ull*)(sm + CC * 256);        // [c][48] duplicated f32x2 pairs

    int b    = blockIdx.y;
    int t0   = blockIdx.x * 256;
    int tid  = threadIdx.x;
    int tq   = tid & 63;            // t = t0 + tq*4
    int jg   = tid >> 6;            // 0..3 -> j offset jg*12

    // stage X[b, 0:60, t0:t0+256] (DRAM read exactly once)
    const float* Xb = X + (size_t)b * CC * TT + t0;
    for (int i = tid; i < CC * 64; i += 256) {
        int c = i >> 6, q = i & 63;
        *(float4*)&Xs[c * 256 + q * 4] = *(const float4*)&Xb[(size_t)c * TT + q * 4];
    }

    float* outb = out + (size_t)b * D1 * TT + t0 + tq * 4;
    const float* xbase = &Xs[tq * 4];
    const ull*   wbase = &ws2[jg * 12];

    for (int iter = 0; iter < 6; iter++) {
        int jbase = iter * JPB;
        __syncthreads();   // protect ws2 (and Xs on iter 0)
        for (int i = tid; i < JPB * CC; i += 256) {
            int r = i / CC, c = i - r * CC;
            int j = jbase + r;
            if (j > D1 - 1) j = D1 - 1;          // clamp (last iter partial)
            float w = g_w[j * CC + c];
            float2 d = make_float2(w, w);
            ws2[c * JPB + r] = *(ull*)&d;
        }
        __syncthreads();

        ull acc[12][2];
#pragma unroll
        for (int r = 0; r < 12; r++) { acc[r][0] = 0ull; acc[r][1] = 0ull; }

#pragma unroll 12
        for (int c = 0; c < CC; c++) {
            ulonglong2 x2 = *(const ulonglong2*)(xbase + c * 256);
            const ulonglong2* wp = (const ulonglong2*)(wbase + c * JPB);
            ulonglong2 w01 = wp[0];
            ulonglong2 w23 = wp[1];
            ulonglong2 w45 = wp[2];
            ulonglong2 w67 = wp[3];
            ulonglong2 w89 = wp[4];
            ulonglong2 wAB = wp[5];
            acc[0][0]  = fma2(x2.x, w01.x, acc[0][0]);
            acc[0][1]  = fma2(x2.y, w01.x, acc[0][1]);
            acc[1][0]  = fma2(x2.x, w01.y, acc[1][0]);
            acc[1][1]  = fma2(x2.y, w01.y, acc[1][1]);
            acc[2][0]  = fma2(x2.x, w23.x, acc[2][0]);
            acc[2][1]  = fma2(x2.y, w23.x, acc[2][1]);
            acc[3][0]  = fma2(x2.x, w23.y, acc[3][0]);
            acc[3][1]  = fma2(x2.y, w23.y, acc[3][1]);
            acc[4][0]  = fma2(x2.x, w45.x, acc[4][0]);
            acc[4][1]  = fma2(x2.y, w45.x, acc[4][1]);
            acc[5][0]  = fma2(x2.x, w45.y, acc[5][0]);
            acc[5][1]  = fma2(x2.y, w45.y, acc[5][1]);
            acc[6][0]  = fma2(x2.x, w67.x, acc[6][0]);
            acc[6][1]  = fma2(x2.y, w67.x, acc[6][1]);
            acc[7][0]  = fma2(x2.x, w67.y, acc[7][0]);
            acc[7][1]  = fma2(x2.y, w67.y, acc[7][1]);
            acc[8][0]  = fma2(x2.x, w89.x, acc[8][0]);
            acc[8][1]  = fma2(x2.y, w89.x, acc[8][1]);
            acc[9][0]  = fma2(x2.x, w89.y, acc[9][0]);
            acc[9][1]  = fma2(x2.y, w89.y, acc[9][1]);
            acc[10][0] = fma2(x2.x, wAB.x, acc[10][0]);
            acc[10][1] = fma2(x2.y, wAB.x, acc[10][1]);
            acc[11][0] = fma2(x2.x, wAB.y, acc[11][0]);
            acc[11][1] = fma2(x2.y, wAB.y, acc[11][1]);
        }

#pragma unroll
        for (int r = 0; r < 12; r++) {
            int j = jbase + jg * 12 + r;
            if (j < D1) {
                double2 o;
                o.x = __longlong_as_double((long long)acc[r][0]);
                o.y = __longlong_as_double((long long)acc[r][1]);
                __stcs((double2*)&outb[(size_t)j * TT], o);   // streaming store
            }
        }
    }
}

// ---------------- launch ----------------
extern "C" void kernel_launch(void* const* d_in, const int* in_sizes, int n_in,
                              void* d_out, int out_size) {
    const float* X    = (const float*)d_in[0];
    const float* z_re = (const float*)d_in[1];
    const float* z_im = (const float*)d_in[2];
    const float* loc  = (const float*)d_in[3];
    float* out = (float*)d_out;

    k_nop<<<1, 32>>>();
    k_tables<<<(KL * CC + 255) / 256, 256>>>(loc);
    k_weights<<<45, 384>>>(z_re, z_im);

    cudaFuncSetAttribute(k_mix, cudaFuncAttributeMaxDynamicSharedMemorySize, SMEM3);
    k_mix<<<dim3(TT / 256, BB), 256, SMEM3>>>(X, out);
}

// round 8
// speedup vs baseline: 1.5786x; 1.5786x over previous
#include <cuda_runtime.h>
#include <cstdint>

typedef unsigned long long ull;

#define D1 270
#define KK 32
#define CC 60
#define BB 64
#define TT 4096
#define KL (KK*KK)        // 1024

// ---------------- scratch (no allocs allowed) ----------------
__device__ float g_cos[KL * CC];   // [kl][c]
__device__ float g_sin[KL * CC];
__device__ float g_w[D1 * CC];     // [j][c]

// ---------------- f32x2 helpers ----------------
__device__ __forceinline__ ull fma2(ull a, ull b, ull c) {
    ull d;
    asm("fma.rn.f32x2 %0, %1, %2, %3;" : "=l"(d) : "l"(a), "l"(b), "l"(c));
    return d;
}
__device__ __forceinline__ ull dup2(float x) {          // (x, x)
    ull d;
    asm("mov.b64 %0, {%1, %1};" : "=l"(d) : "f"(x));
    return d;
}
__device__ __forceinline__ float lo2(ull v) {
    float lo, hi;
    asm("mov.b64 {%0, %1}, %2;" : "=f"(lo), "=f"(hi) : "l"(v));
    return lo;
}
__device__ __forceinline__ float hi2(ull v) {
    float lo, hi;
    asm("mov.b64 {%0, %1}, %2;" : "=f"(lo), "=f"(hi) : "l"(v));
    return hi;
}

// ---------------- K0: alignment dummy (keeps ncu -s 5 -c 1 on k_mix) -------
__global__ void k_nop() {}

// ---------------- K1: sin/cos tables ----------------
__global__ void k_tables(const float* __restrict__ loc) {
    int idx = blockIdx.x * blockDim.x + threadIdx.x;
    if (idx >= KL * CC) return;
    int kl = idx / CC;
    int c  = idx - kl * CC;
    int k = kl >> 5, l = kl & 31;
    float t = (float)k * loc[2 * c] + (float)l * loc[2 * c + 1];
    float s, co;
    sincosf(6.283185307179586f * t, &s, &co);
    g_cos[idx] = co;
    g_sin[idx] = s;
}

// ---------------- K2: a[j,c] + softmax -> g_w -------------------------------
// 135 blocks x 2 j: halves table L2 traffic vs 1 j/block, keeps chip full.
__global__ __launch_bounds__(512) void k_weights(const float* __restrict__ z_re,
                                                 const float* __restrict__ z_im) {
    int tid = threadIdx.x;          // 512 threads
    int c   = tid & 63;
    int s   = tid >> 6;             // 8 kl-slices
    int j0  = blockIdx.x * 2;

    float a0 = 0.f, a1 = 0.f;
    if (c < CC) {
        const float* zr0 = z_re + (size_t)j0 * KL;
        const float* zi0 = z_im + (size_t)j0 * KL;
        const float* zr1 = zr0 + KL;
        const float* zi1 = zi0 + KL;
        for (int kl = s; kl < KL; kl += 8) {
            float co = g_cos[kl * CC + c];
            float si = g_sin[kl * CC + c];
            a0 += zr0[kl] * co + zi0[kl] * si;
            a1 += zr1[kl] * co + zi1[kl] * si;
        }
    }
    __shared__ float sp[8][2][64];
    __shared__ float aval[2][64];
    __shared__ float red[2][2];
    sp[s][0][c] = a0;
    sp[s][1][c] = a1;
    __syncthreads();
    if (tid < 128) {
        int row = tid >> 6, cc = tid & 63;
        float v = 0.f;
#pragma unroll
        for (int i = 0; i < 8; i++) v += sp[i][row][cc];
        aval[row][cc] = v;
    }
    __syncthreads();
    if (tid < 2) {
        int row = tid;
        float m = -1e30f;
        for (int i = 0; i < CC; i++) m = fmaxf(m, aval[row][i]);
        float ssum = 0.f;
        for (int i = 0; i < CC; i++) ssum += expf(aval[row][i] - m);
        red[row][0] = m;
        red[row][1] = ssum;
    }
    __syncthreads();
    if (tid < 128) {
        int row = tid >> 6, cc = tid & 63;
        if (cc < CC)
            g_w[(j0 + row) * CC + cc] = expf(aval[row][cc] - red[row][0]) / red[row][1];
    }
}

// ---------------- K3: out[b,j,t] = sum_c w[j,c] * X[b,c,t] ----------------
// Grid (16,64), block 256 = 64 tq (x4 t) x 4 jg (x12 j as 6 f32x2 j-pairs).
// f32x2 lanes = (j, j+1): w pairs load directly from smem, x is lane-duplicated.
// Per c per thread: 1 LDS.128 X + 3 LDS.128 w(bcast) + 4 dup-MOV + 24 FFMA2.
#define JPB 48                      // j per iteration (6 iters x 48 = 288, pad 18)
#define SMEM3 (CC * 256 * 4 + CC * JPB * 4)   // 61440 + 11520 = 72960 B -> 3 CTAs/SM

__global__ __launch_bounds__(256, 3) void k_mix(const float* __restrict__ X,
                                                float* __restrict__ out) {
    extern __shared__ float sm[];
    float* Xs = sm;                 // [c][256]
    float* ws = sm + CC * 256;      // [c][JPB] plain floats

    int b    = blockIdx.y;
    int t0   = blockIdx.x * 256;
    int tid  = threadIdx.x;
    int tq   = tid & 63;            // t = t0 + tq*4
    int jg   = tid >> 6;            // 0..3 -> j offset jg*12

    // stage X[b, 0:60, t0:t0+256] (DRAM read exactly once)
    const float* Xb = X + (size_t)b * CC * TT + t0;
    for (int i = tid; i < CC * 64; i += 256) {
        int c = i >> 6, q = i & 63;
        *(float4*)&Xs[c * 256 + q * 4] = *(const float4*)&Xb[(size_t)c * TT + q * 4];
    }

    float* outb = out + (size_t)b * D1 * TT + t0 + tq * 4;
    const float* xbase = &Xs[tq * 4];
    const float* wbase = &ws[jg * 12];          // 48B-aligned (16B ok)

    for (int iter = 0; iter < 6; iter++) {
        int jbase = iter * JPB;
        __syncthreads();   // protect ws (and Xs on iter 0)
        for (int i = tid; i < JPB * CC; i += 256) {
            int c = i / JPB, r = i - c * JPB;
            int j = jbase + r;
            if (j > D1 - 1) j = D1 - 1;          // clamp (last iter partial)
            ws[c * JPB + r] = g_w[j * CC + c];
        }
        __syncthreads();

        ull acc[6][4];                           // [j-pair][t]
#pragma unroll
        for (int p = 0; p < 6; p++)
#pragma unroll
            for (int t = 0; t < 4; t++) acc[p][t] = 0ull;

#pragma unroll 10
        for (int c = 0; c < CC; c++) {
            float4 xv = *(const float4*)(xbase + c * 256);
            ull xd[4] = {dup2(xv.x), dup2(xv.y), dup2(xv.z), dup2(xv.w)};
            const ulonglong2* wp = (const ulonglong2*)(wbase + c * JPB);
            ulonglong2 wa = wp[0];               // pairs (w0,w1),(w2,w3)
            ulonglong2 wb = wp[1];               // (w4,w5),(w6,w7)
            ulonglong2 wc = wp[2];               // (w8,w9),(w10,w11)
            ull wpair[6] = {wa.x, wa.y, wb.x, wb.y, wc.x, wc.y};
#pragma unroll
            for (int p = 0; p < 6; p++) {
#pragma unroll
                for (int t = 0; t < 4; t++)
                    acc[p][t] = fma2(xd[t], wpair[p], acc[p][t]);
            }
        }

#pragma unroll
        for (int p = 0; p < 6; p++) {
            int j = jbase + jg * 12 + 2 * p;
            if (j < D1) {
                float4 o0 = make_float4(lo2(acc[p][0]), lo2(acc[p][1]),
                                        lo2(acc[p][2]), lo2(acc[p][3]));
                __stcs((float4*)&outb[(size_t)j * TT], o0);
            }
            if (j + 1 < D1) {
                float4 o1 = make_float4(hi2(acc[p][0]), hi2(acc[p][1]),
                                        hi2(acc[p][2]), hi2(acc[p][3]));
                __stcs((float4*)&outb[(size_t)(j + 1) * TT], o1);
            }
        }
    }
}

// ---------------- launch ----------------
extern "C" void kernel_launch(void* const* d_in, const int* in_sizes, int n_in,
                              void* d_out, int out_size) {
    const float* X    = (const float*)d_in[0];
    const float* z_re = (const float*)d_in[1];
    const float* z_im = (const float*)d_in[2];
    const float* loc  = (const float*)d_in[3];
    float* out = (float*)d_out;

    k_nop<<<1, 32>>>();
    k_tables<<<(KL * CC + 255) / 256, 256>>>(loc);
    k_weights<<<135, 512>>>(z_re, z_im);

    cudaFuncSetAttribute(k_mix, cudaFuncAttributeMaxDynamicSharedMemorySize, SMEM3);
    k_mix<<<dim3(TT / 256, BB), 256, SMEM3>>>(X, out);
}

// round 10
// speedup vs baseline: 1.6056x; 1.0171x over previous
#include <cuda_runtime.h>
#include <cstdint>

typedef unsigned long long ull;

#define D1 270
#define KK 32
#define CC 60
#define BB 64
#define TT 4096
#define KL (KK*KK)        // 1024

// ---------------- scratch (no allocs allowed) ----------------
__device__ float g_cos[KL * CC];   // [kl][c]
__device__ float g_sin[KL * CC];
__device__ float g_wT[CC * D1];    // TRANSPOSED: [c][j] for coalesced k_mix fill

// ---------------- f32x2 helpers ----------------
__device__ __forceinline__ ull fma2(ull a, ull b, ull c) {
    ull d;
    asm("fma.rn.f32x2 %0, %1, %2, %3;" : "=l"(d) : "l"(a), "l"(b), "l"(c));
    return d;
}
__device__ __forceinline__ ull dup2(float x) {          // (x, x)
    ull d;
    asm("mov.b64 %0, {%1, %1};" : "=l"(d) : "f"(x));
    return d;
}
__device__ __forceinline__ float lo2(ull v) {
    float lo, hi;
    asm("mov.b64 {%0, %1}, %2;" : "=f"(lo), "=f"(hi) : "l"(v));
    return lo;
}
__device__ __forceinline__ float hi2(ull v) {
    float lo, hi;
    asm("mov.b64 {%0, %1}, %2;" : "=f"(lo), "=f"(hi) : "l"(v));
    return hi;
}

// ---------------- K0: alignment dummy (keeps ncu -s 5 -c 1 on k_mix) -------
__global__ void k_nop() {}

// ---------------- K1: sin/cos tables ----------------
__global__ void k_tables(const float* __restrict__ loc) {
    int idx = blockIdx.x * blockDim.x + threadIdx.x;
    if (idx >= KL * CC) return;
    int kl = idx / CC;
    int c  = idx - kl * CC;
    int k = kl >> 5, l = kl & 31;
    float t = (float)k * loc[2 * c] + (float)l * loc[2 * c + 1];
    float s, co;
    sincosf(6.283185307179586f * t, &s, &co);
    g_cos[idx] = co;
    g_sin[idx] = s;
}

// ---------------- K2: a[j,c] + softmax -> g_wT (270 blocks x 512 thr) ------
__global__ __launch_bounds__(512) void k_weights(const float* __restrict__ z_re,
                                                 const float* __restrict__ z_im) {
    int j   = blockIdx.x;
    int tid = threadIdx.x;          // 512 threads
    int c   = tid & 63;
    int s   = tid >> 6;             // 8 kl-slices

    float partial = 0.f;
    if (c < CC) {
        const float* zr = z_re + (size_t)j * KL;
        const float* zi = z_im + (size_t)j * KL;
        for (int kl = s; kl < KL; kl += 8) {
            partial += zr[kl] * g_cos[kl * CC + c] + zi[kl] * g_sin[kl * CC + c];
        }
    }
    __shared__ float sp[8][64];
    __shared__ float aval[64];
    __shared__ float red[2];
    sp[s][c] = partial;
    __syncthreads();
    if (tid < 64) {
        float v = 0.f;
#pragma unroll
        for (int i = 0; i < 8; i++) v += sp[i][tid];
        aval[tid] = v;
    }
    __syncthreads();
    if (tid == 0) {
        float m = -1e30f;
        for (int i = 0; i < CC; i++) m = fmaxf(m, aval[i]);
        float ssum = 0.f;
        for (int i = 0; i < CC; i++) ssum += expf(aval[i] - m);
        red[0] = m;
        red[1] = ssum;
    }
    __syncthreads();
    if (tid < CC) {
        g_wT[tid * D1 + j] = expf(aval[tid] - red[0]) / red[1];  // transposed store
    }
}

// ---------------- K3: out[b,j,t] = sum_c w[j,c] * X[b,c,t] ----------------
// Grid (32,64), block 128 = 32 tq (x4 t) x 4 jg (x12 j as 6 f32x2 j-pairs).
// t-tile 128 -> smem 42.2KB -> 5 CTAs/SM (vs 3): waves 2.77 (infl 1.08 vs 1.30).
// f32x2 lanes = (j, j+1): w pairs load directly from smem, x lane-duplicated.
#define JPB 48                      // j per iteration (6 iters x 48 = 288, pad 18)
#define TTILE 128
#define SMEM3 (CC * TTILE * 4 + CC * JPB * 4)   // 30720 + 11520 = 42240 B

__global__ __launch_bounds__(128, 5) void k_mix(const float* __restrict__ X,
                                                float* __restrict__ out) {
    extern __shared__ float sm[];
    float* Xs = sm;                 // [c][128]
    float* ws = sm + CC * TTILE;    // [c][JPB] plain floats

    int b    = blockIdx.y;
    int t0   = blockIdx.x * TTILE;
    int tid  = threadIdx.x;
    int tq   = tid & 31;            // t = t0 + tq*4
    int jg   = tid >> 5;            // 0..3 -> j offset jg*12

    // stage X[b, 0:60, t0:t0+128] (DRAM read exactly once per element)
    const float* Xb = X + (size_t)b * CC * TT + t0;
    for (int i = tid; i < CC * 32; i += 128) {
        int c = i >> 5, q = i & 31;
        *(float4*)&Xs[c * TTILE + q * 4] = *(const float4*)&Xb[(size_t)c * TT + q * 4];
    }

    float* outb = out + (size_t)b * D1 * TT + t0 + tq * 4;
    const float* xbase = &Xs[tq * 4];
    const float* wbase = &ws[jg * 12];

    for (int iter = 0; iter < 6; iter++) {
        int jbase = iter * JPB;
        __syncthreads();   // protect ws (and Xs on iter 0)
        // coalesced fill: g_wT row-contiguous in j
        for (int i = tid; i < JPB * CC; i += 128) {
            int c = i / JPB, r = i - c * JPB;
            int j = jbase + r;
            if (j > D1 - 1) j = D1 - 1;          // clamp (last iter partial)
            ws[c * JPB + r] = g_wT[c * D1 + j];
        }
        __syncthreads();

        ull acc[6][4];                           // [j-pair][t]
#pragma unroll
        for (int p = 0; p < 6; p++)
#pragma unroll
            for (int t = 0; t < 4; t++) acc[p][t] = 0ull;

#pragma unroll 10
        for (int c = 0; c < CC; c++) {
            float4 xv = *(const float4*)(xbase + c * TTILE);
            ull xd[4] = {dup2(xv.x), dup2(xv.y), dup2(xv.z), dup2(xv.w)};
            const ulonglong2* wp = (const ulonglong2*)(wbase + c * JPB);
            ulonglong2 wa = wp[0];               // pairs (w0,w1),(w2,w3)
            ulonglong2 wb = wp[1];               // (w4,w5),(w6,w7)
            ulonglong2 wc = wp[2];               // (w8,w9),(w10,w11)
            ull wpair[6] = {wa.x, wa.y, wb.x, wb.y, wc.x, wc.y};
#pragma unroll
            for (int p = 0; p < 6; p++) {
#pragma unroll
                for (int t = 0; t < 4; t++)
                    acc[p][t] = fma2(xd[t], wpair[p], acc[p][t]);
            }
        }

#pragma unroll
        for (int p = 0; p < 6; p++) {
            int j = jbase + jg * 12 + 2 * p;
            if (j < D1) {
                float4 o0 = make_float4(lo2(acc[p][0]), lo2(acc[p][1]),
                                        lo2(acc[p][2]), lo2(acc[p][3]));
                __stcs((float4*)&outb[(size_t)j * TT], o0);
            }
            if (j + 1 < D1) {
                float4 o1 = make_float4(hi2(acc[p][0]), hi2(acc[p][1]),
                                        hi2(acc[p][2]), hi2(acc[p][3]));
                __stcs((float4*)&outb[(size_t)(j + 1) * TT], o1);
            }
        }
    }
}

// ---------------- launch ----------------
extern "C" void kernel_launch(void* const* d_in, const int* in_sizes, int n_in,
                              void* d_out, int out_size) {
    const float* X    = (const float*)d_in[0];
    const float* z_re = (const float*)d_in[1];
    const float* z_im = (const float*)d_in[2];
    const float* loc  = (const float*)d_in[3];
    float* out = (float*)d_out;

    k_nop<<<1, 32>>>();
    k_tables<<<(KL * CC + 255) / 256, 256>>>(loc);
    k_weights<<<D1, 512>>>(z_re, z_im);

    // allow 5 CTAs/SM worth of shared memory (211KB of the 228KB carveout)
    cudaFuncSetAttribute(k_mix, cudaFuncAttributePreferredSharedMemoryCarveout,
                         cudaSharedmemCarveoutMaxShared);
    k_mix<<<dim3(TT / TTILE, BB), 128, SMEM3>>>(X, out);
}